// round 14
// baseline (speedup 1.0000x reference)
#include <cuda_runtime.h>
#include <cuda_fp16.h>
#include <math.h>
#include <stdint.h>

#define SEQ 2048
#define BATCH 2
#define HIDDEN 4096
#define HD 128
#define HQ 32
#define HKV 8
#define WINDOW 1024
#define NEG_INF_F (-1e30f)
#define MROWS (BATCH * SEQ) /* 4096 */
#define NQ (HQ * HD)        /* 4096 */
#define NKV (HKV * HD)      /* 1024 */

// ---------------- scratch (static device arrays; no allocations) ----------------
__device__ __half g_xn_h[(size_t)MROWS * HIDDEN];
__device__ __half g_wqT[(size_t)NQ * HIDDEN];
__device__ __half g_wkvT[(size_t)2 * NKV * HIDDEN];  // rows 0-1023: Wk^T, 1024-2047: Wv^T
__device__ __half g_woT[(size_t)HIDDEN * NQ];
// head-major fp16 for attention
__device__ __half g_qh[(size_t)BATCH * HQ * SEQ * HD];
__device__ __half g_kh[(size_t)BATCH * HKV * SEQ * HD];
__device__ __half g_vh[(size_t)BATCH * HKV * SEQ * HD];
__device__ __half g_at_h[(size_t)MROWS * NQ];
__device__ float g_cos[SEQ * 64];
__device__ float g_sin[SEQ * 64];

// ---------------- PTX helpers (baseline sm_80+ ISA only) ----------------
__device__ __forceinline__ uint32_t smem_u32(const void* p) {
    uint32_t a;
    asm("{ .reg .u64 t; cvta.to.shared.u64 t, %1; cvt.u32.u64 %0, t; }" : "=r"(a) : "l"(p));
    return a;
}
__device__ __forceinline__ void cp16(uint32_t s, const void* g) {
    asm volatile("cp.async.cg.shared.global [%0], [%1], 16;" :: "r"(s), "l"(g));
}
__device__ __forceinline__ void cp_commit() {
    asm volatile("cp.async.commit_group;" ::: "memory");
}
__device__ __forceinline__ void cp_wait1() {
    asm volatile("cp.async.wait_group 1;" ::: "memory");
}
#define LDSM4(r0, r1, r2, r3, a) \
    asm volatile("ldmatrix.sync.aligned.m8n8.x4.shared.b16 {%0,%1,%2,%3}, [%4];" \
                 : "=r"(r0), "=r"(r1), "=r"(r2), "=r"(r3) : "r"(a))
#define LDSM4T(r0, r1, r2, r3, a) \
    asm volatile("ldmatrix.sync.aligned.m8n8.x4.trans.shared.b16 {%0,%1,%2,%3}, [%4];" \
                 : "=r"(r0), "=r"(r1), "=r"(r2), "=r"(r3) : "r"(a))

__device__ __forceinline__ void mma16816(float* d, const uint32_t* a, uint32_t b0, uint32_t b1) {
    asm volatile(
        "mma.sync.aligned.m16n8k16.row.col.f32.f16.f16.f32 "
        "{%0,%1,%2,%3}, {%4,%5,%6,%7}, {%8,%9}, {%0,%1,%2,%3};"
        : "+f"(d[0]), "+f"(d[1]), "+f"(d[2]), "+f"(d[3])
        : "r"(a[0]), "r"(a[1]), "r"(a[2]), "r"(a[3]), "r"(b0), "r"(b1));
}

__device__ __forceinline__ uint32_t pk2(float a, float b) {
    __half2 t;
    t.x = __float2half_rn(a);
    t.y = __float2half_rn(b);
    return *(uint32_t*)&t;
}

// 50*tanh(s/50) via odd polynomial (pure FMA; clamp guards tails).
__device__ __forceinline__ float captanh(float s) {
    float y = s * s * 4.0e-4f;
    float f = 1.0f + y * (-0.33333334f + y * (0.13333333f + y * (-0.053968254f)));
    float v = s * f;
    return fminf(fmaxf(v, -50.f), 50.f);
}

// ---------------- RMSNorm -> fp16 ----------------
__global__ __launch_bounds__(256) void rmsnorm_kernel(
    const float* __restrict__ x, const float* __restrict__ gamma,
    __half* __restrict__ xh) {
    const int row = blockIdx.x;
    const float4* xr = (const float4*)(x + (size_t)row * HIDDEN);
    const float4* g4 = (const float4*)gamma;

    float ss = 0.f;
    float4 v[4];
#pragma unroll
    for (int i = 0; i < 4; i++) {
        v[i] = xr[threadIdx.x + 256 * i];
        ss += v[i].x * v[i].x + v[i].y * v[i].y + v[i].z * v[i].z + v[i].w * v[i].w;
    }
#pragma unroll
    for (int o = 16; o > 0; o >>= 1) ss += __shfl_xor_sync(~0u, ss, o);
    __shared__ float sred[8];
    if ((threadIdx.x & 31) == 0) sred[threadIdx.x >> 5] = ss;
    __syncthreads();
    float tot = 0.f;
#pragma unroll
    for (int i = 0; i < 8; i++) tot += sred[i];

    const float inv = rsqrtf(tot / (float)HIDDEN + 1e-5f);
    size_t rb = (size_t)row * HIDDEN;
#pragma unroll
    for (int i = 0; i < 4; i++) {
        float4 g = g4[threadIdx.x + 256 * i];
        size_t e = rb + (size_t)(threadIdx.x + 256 * i) * 4;
        __half2 h01, h23;
        h01.x = __float2half_rn(v[i].x * inv * g.x);
        h01.y = __float2half_rn(v[i].y * inv * g.y);
        h23.x = __float2half_rn(v[i].z * inv * g.z);
        h23.y = __float2half_rn(v[i].w * inv * g.w);
        *(__half2*)(xh + e) = h01;
        *(__half2*)(xh + e + 2) = h23;
    }
}

// ---------------- weight transpose + convert: W[K,N] -> T[N,K] fp16 ----------------
__global__ __launch_bounds__(256) void tconv_kernel(
    const float* __restrict__ W, __half* __restrict__ Th, int K, int N) {
    __shared__ __half sh[64][68];
    const int k0 = blockIdx.x * 64, n0 = blockIdx.y * 64;
    const int tid = threadIdx.x;

    for (int i = tid; i < 64 * 16; i += 256) {
        int r = i >> 4;
        int c4 = (i & 15) << 2;
        float4 w = *(const float4*)&W[(size_t)(k0 + r) * N + n0 + c4];
        sh[c4 + 0][r] = __float2half_rn(w.x);
        sh[c4 + 1][r] = __float2half_rn(w.y);
        sh[c4 + 2][r] = __float2half_rn(w.z);
        sh[c4 + 3][r] = __float2half_rn(w.w);
    }
    __syncthreads();
    for (int i = tid; i < 64 * 16; i += 256) {
        int n = i >> 4, kk4 = (i & 15) << 2;
        size_t off = (size_t)(n0 + n) * K + k0 + kk4;
        __half2 a, b;
        a.x = sh[n][kk4]; a.y = sh[n][kk4 + 1];
        b.x = sh[n][kk4 + 2]; b.y = sh[n][kk4 + 3];
        *(__half2*)(Th + off) = a;
        *(__half2*)(Th + off + 2) = b;
    }
}

// ---------------- RoPE tables ----------------
__global__ void rope_table_kernel(float* __restrict__ cosT, float* __restrict__ sinT) {
    int idx = blockIdx.x * blockDim.x + threadIdx.x;
    if (idx >= SEQ * 64) return;
    int s = idx >> 6, i = idx & 63;
    double ang = (double)s * pow(10000.0, -(double)i / 64.0);
    double sn, cs;
    sincos(ang, &sn, &cs);
    cosT[idx] = (float)cs;
    sinT[idx] = (float)sn;
}

// ---------------- mma.sync GEMM, tile 128x128, 3-stage pipeline, fused epilogues ----------------
// mode 0: C fp32 (+R residual)
// mode 1: RoPE + head-major fp16 -> H
// mode 2: head-major fp16 -> H (no rope)
// mode 3: packed KV: head<8 -> rope -> H (K, nh=8); head>=8 -> H2 (V, nh=8)
#define GEMM_SMEM (3 * 32768)

__device__ __forceinline__ void load_sub(uint32_t sdst, const __half* src,
                                         int rbase, int K, int k0, int tid) {
#pragma unroll
    for (int p = 0; p < 4; p++) {
        int u = tid + (p << 8);
        int r = u >> 3, c16 = u & 7;
        const char* g = (const char*)(src + (size_t)(rbase + r) * K + k0) + (c16 << 4);
        cp16(sdst + r * 128 + ((c16 ^ (r & 7)) << 4), g);
    }
}

__global__ __launch_bounds__(256, 2) void gemm_mma(
    const __half* __restrict__ Ah, const __half* __restrict__ Bh,
    const float* __restrict__ R, float* __restrict__ C,
    __half* __restrict__ H, __half* __restrict__ H2, int mode, int M, int N, int K) {
    extern __shared__ char smraw[];
    const uint32_t sbase = smem_u32(smraw);
    const int tid = threadIdx.x;
    const int lane = tid & 31, wid = tid >> 5;
    const int row0 = blockIdx.y * 128, col0 = blockIdx.x * 128;
    const int wm = (wid & 1) * 64, wn = (wid >> 1) * 32;

    float acc[4][4][4];
#pragma unroll
    for (int i = 0; i < 4; i++)
#pragma unroll
        for (int j = 0; j < 4; j++)
#pragma unroll
            for (int r = 0; r < 4; r++) acc[i][j][r] = 0.f;

    const int NC = K >> 6;

    // prologue: chunks 0 and 1 in flight
    load_sub(sbase,         Ah, row0, K, 0, tid);
    load_sub(sbase + 16384, Bh, col0, K, 0, tid);
    cp_commit();
    if (NC > 1) {
        load_sub(sbase + 32768,         Ah, row0, K, 64, tid);
        load_sub(sbase + 32768 + 16384, Bh, col0, K, 64, tid);
        cp_commit();
    }

    const int a_r = lane & 15;
    const int a_ch = lane >> 4;
    const int b_n = ((lane >> 4) << 3) + (lane & 7);
    const int b_kh = (lane >> 3) & 1;

    for (int c = 0; c < NC; c++) {
        cp_wait1();        // oldest pending (chunk c) complete
        __syncthreads();   // buf c visible; buf (c+2)%3 free (all warps done with c-1)
        if (c + 2 < NC) {
            const uint32_t nb = sbase + ((c + 2) % 3) * 32768;
            const int k0 = (c + 2) << 6;
            load_sub(nb,         Ah, row0, K, k0, tid);
            load_sub(nb + 16384, Bh, col0, K, k0, tid);
            cp_commit();
        }

        const uint32_t sb = sbase + (c % 3) * 32768;
#pragma unroll
        for (int ks = 0; ks < 4; ks++) {
            uint32_t aH[4][4], bH[2][4];
#pragma unroll
            for (int i = 0; i < 4; i++) {
                int r = wm + i * 16 + a_r;
                uint32_t cl = (uint32_t)((ks * 2 + a_ch) ^ (r & 7)) << 4;
                LDSM4(aH[i][0], aH[i][1], aH[i][2], aH[i][3], sb + r * 128 + cl);
            }
#pragma unroll
            for (int j = 0; j < 2; j++) {
                int r = wn + j * 16 + b_n;
                uint32_t cl = (uint32_t)((ks * 2 + b_kh) ^ (r & 7)) << 4;
                LDSM4(bH[j][0], bH[j][1], bH[j][2], bH[j][3], sb + 16384 + r * 128 + cl);
            }
#pragma unroll
            for (int i = 0; i < 4; i++) {
#pragma unroll
                for (int jn = 0; jn < 4; jn++) {
                    mma16816(acc[i][jn], aH[i],
                             bH[jn >> 1][(jn & 1) * 2], bH[jn >> 1][(jn & 1) * 2 + 1]);
                }
            }
        }
    }
    __syncthreads();  // protect smem reuse in epilogue

    const int mrow = lane >> 2, ncol = (lane & 3) * 2;
    const int headraw = col0 >> 7;
    int emode = mode;
    int head = headraw;
    int nh = N >> 7;
    __half* Hd = H;
    if (mode == 3) {
        nh = 8;
        if (headraw < 8) { emode = 1; }
        else             { emode = 2; head = headraw - 8; Hd = H2; }
    }

    if (emode == 0) {
#pragma unroll
        for (int i = 0; i < 4; i++) {
            int gr = row0 + wm + i * 16 + mrow;
#pragma unroll
            for (int jn = 0; jn < 4; jn++) {
                int gc = col0 + wn + jn * 8 + ncol;
                float2 v0 = make_float2(acc[i][jn][0], acc[i][jn][1]);
                float2 v1 = make_float2(acc[i][jn][2], acc[i][jn][3]);
                if (R) {
                    float2 r0 = *(const float2*)&R[(size_t)gr * N + gc];
                    float2 r1 = *(const float2*)&R[(size_t)(gr + 8) * N + gc];
                    v0.x += r0.x; v0.y += r0.y;
                    v1.x += r1.x; v1.y += r1.y;
                }
                *(float2*)&C[(size_t)gr * N + gc] = v0;
                *(float2*)&C[(size_t)(gr + 8) * N + gc] = v1;
            }
        }
    } else if (emode == 2) {
#pragma unroll
        for (int i = 0; i < 4; i++) {
            int gr = row0 + wm + i * 16 + mrow;
            int s0 = gr & (SEQ - 1), b0 = gr >> 11;
            int s1 = (gr + 8) & (SEQ - 1), b1 = (gr + 8) >> 11;
#pragma unroll
            for (int jn = 0; jn < 4; jn++) {
                int d = wn + jn * 8 + ncol;
                *(uint32_t*)(Hd + (((size_t)b0 * nh + head) * SEQ + s0) * HD + d) =
                    pk2(acc[i][jn][0], acc[i][jn][1]);
                *(uint32_t*)(Hd + (((size_t)b1 * nh + head) * SEQ + s1) * HD + d) =
                    pk2(acc[i][jn][2], acc[i][jn][3]);
            }
        }
    } else {
        // emode 1: stage to smem (XOR-swizzled float2), rope pairs (d, d+64), fp16 head-major
        float2* F2 = (float2*)smraw;
#pragma unroll
        for (int i = 0; i < 4; i++) {
            int rl0 = wm + i * 16 + mrow;
            int rl1 = rl0 + 8;
#pragma unroll
            for (int jn = 0; jn < 4; jn++) {
                int c2 = (wn + jn * 8 + ncol) >> 1;
                F2[rl0 * 64 + (c2 ^ (rl0 & 15))] = make_float2(acc[i][jn][0], acc[i][jn][1]);
                F2[rl1 * 64 + (c2 ^ (rl1 & 15))] = make_float2(acc[i][jn][2], acc[i][jn][3]);
            }
        }
        __syncthreads();

#pragma unroll
        for (int pass = 0; pass < 16; pass++) {
            int r = pass * 8 + (tid >> 5);
            float2 t1 = F2[r * 64 + (lane ^ (r & 15))];
            float2 t2 = F2[r * 64 + ((lane + 32) ^ (r & 15))];
            int d = lane * 2;
            int grow = row0 + r;
            int s = grow & (SEQ - 1), bb = grow >> 11;
            float ca = g_cos[s * 64 + d], cb = g_cos[s * 64 + d + 1];
            float sa = g_sin[s * 64 + d], sb = g_sin[s * 64 + d + 1];
            size_t base = (((size_t)bb * nh + head) * SEQ + s) * HD;
            *(uint32_t*)(Hd + base + d) = pk2(t1.x * ca - t2.x * sa, t1.y * cb - t2.y * sb);
            *(uint32_t*)(Hd + base + d + 64) = pk2(t2.x * ca + t1.x * sa, t2.y * cb + t1.y * sb);
        }
    }
}

// ---------------- attention via mma.sync (fp16), 3-stage KV pipeline ----------------
// smem: Q 32K | 3x{K 16K|V 16K} = 128KB
#define AT_SMEM (131072)

__device__ __forceinline__ void attn_load_kv(uint32_t dst, const __half* Kh,
                                             const __half* Vh, size_t kb, int tid) {
#pragma unroll
    for (int p = 0; p < 4; p++) {
        int u = tid + (p << 8);
        int r = u >> 4, c = u & 15;
        uint32_t off = r * 256 + (uint32_t)((c ^ (r & 7)) << 4);
        size_t go = (size_t)r * 256 + c * 16;
        cp16(dst + off, (const char*)(Kh + kb) + go);
        cp16(dst + 16384 + off, (const char*)(Vh + kb) + go);
    }
}

__global__ __launch_bounds__(256) void attn_mma(
    const __half* __restrict__ Qh, const __half* __restrict__ Kh,
    const __half* __restrict__ Vh, __half* __restrict__ Oh) {
    extern __shared__ char smraw[];
    const uint32_t S0 = smem_u32(smraw);
    const int tid = threadIdx.x;
    const int lane = tid & 31, wid = tid >> 5;
    const int qt = blockIdx.x, h = blockIdx.y, b = blockIdx.z;
    const int g = h >> 2;
    const int q0 = qt * 128;
    const int m0 = wid * 16;

    {
        const char* qb = (const char*)(Qh + (((size_t)b * HQ + h) * SEQ + q0) * HD);
#pragma unroll
        for (int p = 0; p < 8; p++) {
            int u = tid + (p << 8);
            int r = u >> 4, c = u & 15;
            cp16(S0 + r * 256 + (uint32_t)((c ^ (r & 7)) << 4), qb + r * 256 + c * 16);
        }
    }

    const size_t kvhead = ((size_t)b * HKV + g) * SEQ;
    const int kt_lo = max(0, q0 - WINDOW + 1) >> 6;
    const int kt_hi = (q0 + 127) >> 6;  // nt >= 2 always

    // prologue: tiles kt_lo (with Q in same group) and kt_lo+1
    attn_load_kv(S0 + 32768, Kh, Vh, (kvhead + (size_t)kt_lo * 64) * HD, tid);
    cp_commit();
    attn_load_kv(S0 + 32768 + 32768, Kh, Vh, (kvhead + (size_t)(kt_lo + 1) * 64) * HD, tid);
    cp_commit();

    float acc[16][4];
#pragma unroll
    for (int i = 0; i < 16; i++)
#pragma unroll
        for (int j = 0; j < 4; j++) acc[i][j] = 0.f;
    float m_run0 = NEG_INF_F, m_run1 = NEG_INF_F, l_run0 = 0.f, l_run1 = 0.f;

    const int r0g = q0 + m0 + (lane >> 2);
    const int r1g = r0g + 8;
    const float qscale = 0.08838834764831845f;  // 1/sqrt(128)

    const int a_r = lane & 15;
    const int a_ch = lane >> 4;
    const int sb_r = (lane & 7) + ((lane & 16) >> 1);
    const int sb_c = (lane >> 3) & 1;
    const int pv_r = (lane & 7) + (lane & 8);
    const int pv_c = (lane & 16) >> 4;

    for (int kt = kt_lo; kt <= kt_hi; kt++) {
        const int idx = kt - kt_lo;
        cp_wait1();        // oldest tile (idx) complete (Q included in group 0)
        __syncthreads();   // buf idx visible; buf (idx+2)%3 free
        if (kt + 2 <= kt_hi) {
            attn_load_kv(S0 + 32768 + ((idx + 2) % 3) * 32768, Kh, Vh,
                         (kvhead + (size_t)(kt + 2) * 64) * HD, tid);
            cp_commit();
        }

        const uint32_t KB = S0 + 32768 + (idx % 3) * 32768;

        float S[8][4];
#pragma unroll
        for (int i = 0; i < 8; i++)
#pragma unroll
            for (int j = 0; j < 4; j++) S[i][j] = 0.f;

#pragma unroll
        for (int kc = 0; kc < 8; kc++) {
            uint32_t aH[4];
            {
                int r = m0 + a_r;
                uint32_t cl = (uint32_t)((2 * kc + a_ch) ^ (r & 7)) << 4;
                LDSM4(aH[0], aH[1], aH[2], aH[3], S0 + r * 256 + cl);
            }
#pragma unroll
            for (int np = 0; np < 4; np++) {
                int rr = np * 16 + sb_r;
                uint32_t cl = (uint32_t)((2 * kc + sb_c) ^ (rr & 7)) << 4;
                uint32_t bh0, bh1, bh2, bh3;
                LDSM4(bh0, bh1, bh2, bh3, KB + rr * 256 + cl);
                mma16816(S[2 * np], aH, bh0, bh1);
                mma16816(S[2 * np + 1], aH, bh2, bh3);
            }
        }

        // ---- poly tanh cap + mask + online softmax ----
        const int k0g = kt * 64;
        float mx0 = NEG_INF_F, mx1 = NEG_INF_F;
#pragma unroll
        for (int a = 0; a < 8; a++) {
            int cb = k0g + 8 * a + ((lane & 3) << 1);
            float v0 = captanh(S[a][0] * qscale);
            float v1 = captanh(S[a][1] * qscale);
            float v2 = captanh(S[a][2] * qscale);
            float v3 = captanh(S[a][3] * qscale);
            bool m00 = (cb <= r0g) && (cb > r0g - WINDOW);
            bool m01 = (cb + 1 <= r0g) && (cb + 1 > r0g - WINDOW);
            bool m10 = (cb <= r1g) && (cb > r1g - WINDOW);
            bool m11 = (cb + 1 <= r1g) && (cb + 1 > r1g - WINDOW);
            S[a][0] = m00 ? v0 : NEG_INF_F;
            S[a][1] = m01 ? v1 : NEG_INF_F;
            S[a][2] = m10 ? v2 : NEG_INF_F;
            S[a][3] = m11 ? v3 : NEG_INF_F;
            mx0 = fmaxf(mx0, fmaxf(S[a][0], S[a][1]));
            mx1 = fmaxf(mx1, fmaxf(S[a][2], S[a][3]));
        }
        mx0 = fmaxf(mx0, __shfl_xor_sync(~0u, mx0, 1));
        mx0 = fmaxf(mx0, __shfl_xor_sync(~0u, mx0, 2));
        mx1 = fmaxf(mx1, __shfl_xor_sync(~0u, mx1, 1));
        mx1 = fmaxf(mx1, __shfl_xor_sync(~0u, mx1, 2));

        float mn0 = fmaxf(m_run0, mx0), mn1 = fmaxf(m_run1, mx1);
        float cor0 = __expf(m_run0 - mn0), cor1 = __expf(m_run1 - mn1);
        float sum0 = 0.f, sum1 = 0.f;
#pragma unroll
        for (int a = 0; a < 8; a++) {
            float p0 = (S[a][0] > -1e29f) ? __expf(S[a][0] - mn0) : 0.f;
            float p1 = (S[a][1] > -1e29f) ? __expf(S[a][1] - mn0) : 0.f;
            float p2 = (S[a][2] > -1e29f) ? __expf(S[a][2] - mn1) : 0.f;
            float p3 = (S[a][3] > -1e29f) ? __expf(S[a][3] - mn1) : 0.f;
            S[a][0] = p0; S[a][1] = p1; S[a][2] = p2; S[a][3] = p3;
            sum0 += p0 + p1;
            sum1 += p2 + p3;
        }
        sum0 += __shfl_xor_sync(~0u, sum0, 1);
        sum0 += __shfl_xor_sync(~0u, sum0, 2);
        sum1 += __shfl_xor_sync(~0u, sum1, 1);
        sum1 += __shfl_xor_sync(~0u, sum1, 2);
        l_run0 = l_run0 * cor0 + sum0;
        l_run1 = l_run1 * cor1 + sum1;
        m_run0 = mn0;
        m_run1 = mn1;
#pragma unroll
        for (int i = 0; i < 16; i++) {
            acc[i][0] *= cor0; acc[i][1] *= cor0;
            acc[i][2] *= cor1; acc[i][3] *= cor1;
        }

        uint32_t pH[4][4];
#pragma unroll
        for (int j = 0; j < 4; j++) {
#pragma unroll
            for (int e = 0; e < 2; e++) {
                int a = 2 * j + e;
                pH[j][0 + 2 * e] = pk2(S[a][0], S[a][1]);
                pH[j][1 + 2 * e] = pk2(S[a][2], S[a][3]);
            }
        }

        const uint32_t VB = KB + 16384;
#pragma unroll
        for (int j = 0; j < 4; j++) {
            int kr = j * 16 + pv_r;
#pragma unroll
            for (int dp = 0; dp < 8; dp++) {
                uint32_t cch = (uint32_t)(2 * dp + pv_c);
                uint32_t addr = VB + kr * 256 + (((cch ^ (kr & 7))) << 4);
                uint32_t bh0, bh1, bh2, bh3;
                LDSM4T(bh0, bh1, bh2, bh3, addr);
                mma16816(acc[2 * dp], pH[j], bh0, bh1);
                mma16816(acc[2 * dp + 1], pH[j], bh2, bh3);
            }
        }
    }

    const float inv0 = 1.f / l_run0, inv1 = 1.f / l_run1;
    const size_t gr0 = (size_t)b * SEQ + q0 + m0 + (lane >> 2);
    const size_t gr1 = gr0 + 8;
    const int colb = h * HD + ((lane & 3) << 1);
#pragma unroll
    for (int nd = 0; nd < 16; nd++) {
        int col = colb + nd * 8;
        *(uint32_t*)(Oh + gr0 * NQ + col) = pk2(acc[nd][0] * inv0, acc[nd][1] * inv0);
        *(uint32_t*)(Oh + gr1 * NQ + col) = pk2(acc[nd][2] * inv1, acc[nd][3] * inv1);
    }
}

// ---------------- launch ----------------
extern "C" void kernel_launch(void* const* d_in, const int* in_sizes, int n_in,
                              void* d_out, int out_size) {
    const float* x = (const float*)d_in[0];
    const float* gamma = (const float*)d_in[1];
    const float* Wq = (const float*)d_in[2];
    const float* Wk = (const float*)d_in[3];
    const float* Wv = (const float*)d_in[4];
    const float* Wo = (const float*)d_in[5];
    float* out = (float*)d_out;

    __half *xnh, *wq, *wkv, *wo, *ath, *qh, *kh, *vh;
    float *cosT, *sinT;
    cudaGetSymbolAddress((void**)&xnh, g_xn_h);
    cudaGetSymbolAddress((void**)&wq, g_wqT);
    cudaGetSymbolAddress((void**)&wkv, g_wkvT);
    cudaGetSymbolAddress((void**)&wo, g_woT);
    cudaGetSymbolAddress((void**)&ath, g_at_h);
    cudaGetSymbolAddress((void**)&qh, g_qh);
    cudaGetSymbolAddress((void**)&kh, g_kh);
    cudaGetSymbolAddress((void**)&vh, g_vh);
    cudaGetSymbolAddress((void**)&cosT, g_cos);
    cudaGetSymbolAddress((void**)&sinT, g_sin);

    cudaFuncSetAttribute(gemm_mma, cudaFuncAttributeMaxDynamicSharedMemorySize, GEMM_SMEM);
    cudaFuncSetAttribute(attn_mma, cudaFuncAttributeMaxDynamicSharedMemorySize, AT_SMEM);

    // RoPE tables first (consumed by GEMM epilogues)
    rope_table_kernel<<<(SEQ * 64 + 255) / 256, 256>>>(cosT, sinT);

    // weight convert+transpose (Wk, Wv into packed halves of wkv)
    {
        dim3 gq(HIDDEN / 64, NQ / 64);
        tconv_kernel<<<gq, 256>>>(Wq, wq, HIDDEN, NQ);
        dim3 gk(HIDDEN / 64, NKV / 64);
        tconv_kernel<<<gk, 256>>>(Wk, wkv, HIDDEN, NKV);
        tconv_kernel<<<gk, 256>>>(Wv, wkv + (size_t)NKV * HIDDEN, HIDDEN, NKV);
        dim3 go(NQ / 64, HIDDEN / 64);
        tconv_kernel<<<go, 256>>>(Wo, wo, NQ, HIDDEN);
    }

    // RMSNorm
    rmsnorm_kernel<<<MROWS, 256>>>(x, gamma, xnh);

    // Q projection (rope epilogue) + fused KV projection (mode 3)
    {
        dim3 gq(NQ / 128, MROWS / 128);
        gemm_mma<<<gq, 256, GEMM_SMEM>>>(xnh, wq, (const float*)0, (float*)0, qh, (__half*)0,
                                         1, MROWS, NQ, HIDDEN);
        dim3 gkv(2 * NKV / 128, MROWS / 128);
        gemm_mma<<<gkv, 256, GEMM_SMEM>>>(xnh, wkv, (const float*)0, (float*)0, kh, vh,
                                          3, MROWS, 2 * NKV, HIDDEN);
    }

    // attention
    {
        dim3 ga(SEQ / 128, HQ, BATCH);
        attn_mma<<<ga, 256, AT_SMEM>>>(qh, kh, vh, ath);
    }

    // output projection + residual
    {
        dim3 go(HIDDEN / 128, MROWS / 128);
        gemm_mma<<<go, 256, GEMM_SMEM>>>(ath, wo, x, out, (__half*)0, (__half*)0,
                                         0, MROWS, HIDDEN, NQ);
    }
}

// round 15
// speedup vs baseline: 1.0571x; 1.0571x over previous
#include <cuda_runtime.h>
#include <cuda_fp16.h>
#include <math.h>
#include <stdint.h>

#define SEQ 2048
#define BATCH 2
#define HIDDEN 4096
#define HD 128
#define HQ 32
#define HKV 8
#define WINDOW 1024
#define NEG_INF_F (-1e30f)
#define MROWS (BATCH * SEQ) /* 4096 */
#define NQ (HQ * HD)        /* 4096 */
#define NKV (HKV * HD)      /* 1024 */
#define NQKV (NQ + 2 * NKV) /* 6144 */

// ---------------- scratch (static device arrays; no allocations) ----------------
__device__ __half g_xn_h[(size_t)MROWS * HIDDEN];
__device__ __half g_wqkvT[(size_t)NQKV * HIDDEN];  // rows 0-4095 Wq^T | 4096-5119 Wk^T | 5120-6143 Wv^T
__device__ __half g_woT[(size_t)HIDDEN * NQ];
// head-major fp16 for attention
__device__ __half g_qh[(size_t)BATCH * HQ * SEQ * HD];
__device__ __half g_kh[(size_t)BATCH * HKV * SEQ * HD];
__device__ __half g_vh[(size_t)BATCH * HKV * SEQ * HD];
__device__ __half g_at_h[(size_t)MROWS * NQ];
__device__ float g_cos[SEQ * 64];
__device__ float g_sin[SEQ * 64];

// ---------------- PTX helpers (baseline sm_80+ ISA only) ----------------
__device__ __forceinline__ uint32_t smem_u32(const void* p) {
    uint32_t a;
    asm("{ .reg .u64 t; cvta.to.shared.u64 t, %1; cvt.u32.u64 %0, t; }" : "=r"(a) : "l"(p));
    return a;
}
__device__ __forceinline__ void cp16(uint32_t s, const void* g) {
    asm volatile("cp.async.cg.shared.global [%0], [%1], 16;" :: "r"(s), "l"(g));
}
__device__ __forceinline__ void cp_commit() {
    asm volatile("cp.async.commit_group;" ::: "memory");
}
__device__ __forceinline__ void cp_wait0() {
    asm volatile("cp.async.wait_group 0;" ::: "memory");
}
__device__ __forceinline__ void cp_wait1() {
    asm volatile("cp.async.wait_group 1;" ::: "memory");
}
#define LDSM4(r0, r1, r2, r3, a) \
    asm volatile("ldmatrix.sync.aligned.m8n8.x4.shared.b16 {%0,%1,%2,%3}, [%4];" \
                 : "=r"(r0), "=r"(r1), "=r"(r2), "=r"(r3) : "r"(a))
#define LDSM4T(r0, r1, r2, r3, a) \
    asm volatile("ldmatrix.sync.aligned.m8n8.x4.trans.shared.b16 {%0,%1,%2,%3}, [%4];" \
                 : "=r"(r0), "=r"(r1), "=r"(r2), "=r"(r3) : "r"(a))

__device__ __forceinline__ void mma16816(float* d, const uint32_t* a, uint32_t b0, uint32_t b1) {
    asm volatile(
        "mma.sync.aligned.m16n8k16.row.col.f32.f16.f16.f32 "
        "{%0,%1,%2,%3}, {%4,%5,%6,%7}, {%8,%9}, {%0,%1,%2,%3};"
        : "+f"(d[0]), "+f"(d[1]), "+f"(d[2]), "+f"(d[3])
        : "r"(a[0]), "r"(a[1]), "r"(a[2]), "r"(a[3]), "r"(b0), "r"(b1));
}

__device__ __forceinline__ uint32_t pk2(float a, float b) {
    __half2 t;
    t.x = __float2half_rn(a);
    t.y = __float2half_rn(b);
    return *(uint32_t*)&t;
}

// 50*tanh(s/50) via odd polynomial (pure FMA; clamp guards tails).
__device__ __forceinline__ float captanh(float s) {
    float y = s * s * 4.0e-4f;
    float f = 1.0f + y * (-0.33333334f + y * (0.13333333f + y * (-0.053968254f)));
    float v = s * f;
    return fminf(fmaxf(v, -50.f), 50.f);
}

// ---------------- RMSNorm -> fp16 ----------------
__global__ __launch_bounds__(256) void rmsnorm_kernel(
    const float* __restrict__ x, const float* __restrict__ gamma,
    __half* __restrict__ xh) {
    const int row = blockIdx.x;
    const float4* xr = (const float4*)(x + (size_t)row * HIDDEN);
    const float4* g4 = (const float4*)gamma;

    float ss = 0.f;
    float4 v[4];
#pragma unroll
    for (int i = 0; i < 4; i++) {
        v[i] = xr[threadIdx.x + 256 * i];
        ss += v[i].x * v[i].x + v[i].y * v[i].y + v[i].z * v[i].z + v[i].w * v[i].w;
    }
#pragma unroll
    for (int o = 16; o > 0; o >>= 1) ss += __shfl_xor_sync(~0u, ss, o);
    __shared__ float sred[8];
    if ((threadIdx.x & 31) == 0) sred[threadIdx.x >> 5] = ss;
    __syncthreads();
    float tot = 0.f;
#pragma unroll
    for (int i = 0; i < 8; i++) tot += sred[i];

    const float inv = rsqrtf(tot / (float)HIDDEN + 1e-5f);
    size_t rb = (size_t)row * HIDDEN;
#pragma unroll
    for (int i = 0; i < 4; i++) {
        float4 g = g4[threadIdx.x + 256 * i];
        size_t e = rb + (size_t)(threadIdx.x + 256 * i) * 4;
        __half2 h01, h23;
        h01.x = __float2half_rn(v[i].x * inv * g.x);
        h01.y = __float2half_rn(v[i].y * inv * g.y);
        h23.x = __float2half_rn(v[i].z * inv * g.z);
        h23.y = __float2half_rn(v[i].w * inv * g.w);
        *(__half2*)(xh + e) = h01;
        *(__half2*)(xh + e + 2) = h23;
    }
}

// ---------------- weight transpose + convert: W[K,N] -> T[N,K] fp16 ----------------
__global__ __launch_bounds__(256) void tconv_kernel(
    const float* __restrict__ W, __half* __restrict__ Th, int K, int N) {
    __shared__ __half sh[64][68];
    const int k0 = blockIdx.x * 64, n0 = blockIdx.y * 64;
    const int tid = threadIdx.x;

    for (int i = tid; i < 64 * 16; i += 256) {
        int r = i >> 4;
        int c4 = (i & 15) << 2;
        float4 w = *(const float4*)&W[(size_t)(k0 + r) * N + n0 + c4];
        sh[c4 + 0][r] = __float2half_rn(w.x);
        sh[c4 + 1][r] = __float2half_rn(w.y);
        sh[c4 + 2][r] = __float2half_rn(w.z);
        sh[c4 + 3][r] = __float2half_rn(w.w);
    }
    __syncthreads();
    for (int i = tid; i < 64 * 16; i += 256) {
        int n = i >> 4, kk4 = (i & 15) << 2;
        size_t off = (size_t)(n0 + n) * K + k0 + kk4;
        __half2 a, b;
        a.x = sh[n][kk4]; a.y = sh[n][kk4 + 1];
        b.x = sh[n][kk4 + 2]; b.y = sh[n][kk4 + 3];
        *(__half2*)(Th + off) = a;
        *(__half2*)(Th + off + 2) = b;
    }
}

// ---------------- RoPE tables ----------------
__global__ void rope_table_kernel(float* __restrict__ cosT, float* __restrict__ sinT) {
    int idx = blockIdx.x * blockDim.x + threadIdx.x;
    if (idx >= SEQ * 64) return;
    int s = idx >> 6, i = idx & 63;
    double ang = (double)s * pow(10000.0, -(double)i / 64.0);
    double sn, cs;
    sincos(ang, &sn, &cs);
    cosT[idx] = (float)cs;
    sinT[idx] = (float)sn;
}

// ---------------- mma.sync GEMM, tile 128x128, 2-stage pipeline, fused epilogues ----------------
// mode 0: C fp32 (+R residual)
// mode 4: fused QKV: head<32 -> rope -> H (Q, nh=32); head 32-39 -> rope -> H2 (K, nh=8);
//         head 40-47 -> plain fp16 -> H3 (V, nh=8)
#define GEMM_SMEM (2 * 32768)

__device__ __forceinline__ void load_sub(uint32_t sdst, const __half* src,
                                         int rbase, int K, int k0, int tid) {
#pragma unroll
    for (int p = 0; p < 4; p++) {
        int u = tid + (p << 8);
        int r = u >> 3, c16 = u & 7;
        const char* g = (const char*)(src + (size_t)(rbase + r) * K + k0) + (c16 << 4);
        cp16(sdst + r * 128 + ((c16 ^ (r & 7)) << 4), g);
    }
}

__global__ __launch_bounds__(256, 2) void gemm_mma(
    const __half* __restrict__ Ah, const __half* __restrict__ Bh,
    const float* __restrict__ R, float* __restrict__ C,
    __half* __restrict__ H, __half* __restrict__ H2, __half* __restrict__ H3,
    int mode, int M, int N, int K) {
    extern __shared__ char smraw[];
    const uint32_t sbase = smem_u32(smraw);
    const int tid = threadIdx.x;
    const int lane = tid & 31, wid = tid >> 5;
    const int row0 = blockIdx.y * 128, col0 = blockIdx.x * 128;
    const int wm = (wid & 1) * 64, wn = (wid >> 1) * 32;

    float acc[4][4][4];
#pragma unroll
    for (int i = 0; i < 4; i++)
#pragma unroll
        for (int j = 0; j < 4; j++)
#pragma unroll
            for (int r = 0; r < 4; r++) acc[i][j][r] = 0.f;

    const int NC = K >> 6;

    load_sub(sbase,         Ah, row0, K, 0, tid);
    load_sub(sbase + 16384, Bh, col0, K, 0, tid);
    cp_commit();

    const int a_r = lane & 15;
    const int a_ch = lane >> 4;
    const int b_n = ((lane >> 4) << 3) + (lane & 7);
    const int b_kh = (lane >> 3) & 1;

    for (int c = 0; c < NC; c++) {
        const int buf = c & 1;
        if (c + 1 < NC) {
            const uint32_t nb = sbase + (buf ^ 1) * 32768;
            const int k0 = (c + 1) << 6;
            load_sub(nb,         Ah, row0, K, k0, tid);
            load_sub(nb + 16384, Bh, col0, K, k0, tid);
            cp_commit();
            cp_wait1();
        } else {
            cp_wait0();
        }
        __syncthreads();

        const uint32_t sb = sbase + buf * 32768;
#pragma unroll
        for (int ks = 0; ks < 4; ks++) {
            uint32_t aH[4][4], bH[2][4];
#pragma unroll
            for (int i = 0; i < 4; i++) {
                int r = wm + i * 16 + a_r;
                uint32_t cl = (uint32_t)((ks * 2 + a_ch) ^ (r & 7)) << 4;
                LDSM4(aH[i][0], aH[i][1], aH[i][2], aH[i][3], sb + r * 128 + cl);
            }
#pragma unroll
            for (int j = 0; j < 2; j++) {
                int r = wn + j * 16 + b_n;
                uint32_t cl = (uint32_t)((ks * 2 + b_kh) ^ (r & 7)) << 4;
                LDSM4(bH[j][0], bH[j][1], bH[j][2], bH[j][3], sb + 16384 + r * 128 + cl);
            }
#pragma unroll
            for (int i = 0; i < 4; i++) {
#pragma unroll
                for (int jn = 0; jn < 4; jn++) {
                    mma16816(acc[i][jn], aH[i],
                             bH[jn >> 1][(jn & 1) * 2], bH[jn >> 1][(jn & 1) * 2 + 1]);
                }
            }
        }
        __syncthreads();
    }

    const int mrow = lane >> 2, ncol = (lane & 3) * 2;
    const int headraw = col0 >> 7;
    int emode, head, nh;
    __half* Hd;
    if (mode == 4) {
        if (headraw < 32)      { emode = 1; head = headraw;      nh = HQ; Hd = H; }
        else if (headraw < 40) { emode = 1; head = headraw - 32; nh = 8;  Hd = H2; }
        else                   { emode = 2; head = headraw - 40; nh = 8;  Hd = H3; }
    } else {
        emode = mode; head = headraw; nh = N >> 7; Hd = H;
    }

    if (emode == 0) {
#pragma unroll
        for (int i = 0; i < 4; i++) {
            int gr = row0 + wm + i * 16 + mrow;
#pragma unroll
            for (int jn = 0; jn < 4; jn++) {
                int gc = col0 + wn + jn * 8 + ncol;
                float2 v0 = make_float2(acc[i][jn][0], acc[i][jn][1]);
                float2 v1 = make_float2(acc[i][jn][2], acc[i][jn][3]);
                if (R) {
                    float2 r0 = *(const float2*)&R[(size_t)gr * N + gc];
                    float2 r1 = *(const float2*)&R[(size_t)(gr + 8) * N + gc];
                    v0.x += r0.x; v0.y += r0.y;
                    v1.x += r1.x; v1.y += r1.y;
                }
                *(float2*)&C[(size_t)gr * N + gc] = v0;
                *(float2*)&C[(size_t)(gr + 8) * N + gc] = v1;
            }
        }
    } else if (emode == 2) {
#pragma unroll
        for (int i = 0; i < 4; i++) {
            int gr = row0 + wm + i * 16 + mrow;
            int s0 = gr & (SEQ - 1), b0 = gr >> 11;
            int s1 = (gr + 8) & (SEQ - 1), b1 = (gr + 8) >> 11;
#pragma unroll
            for (int jn = 0; jn < 4; jn++) {
                int d = wn + jn * 8 + ncol;
                *(uint32_t*)(Hd + (((size_t)b0 * nh + head) * SEQ + s0) * HD + d) =
                    pk2(acc[i][jn][0], acc[i][jn][1]);
                *(uint32_t*)(Hd + (((size_t)b1 * nh + head) * SEQ + s1) * HD + d) =
                    pk2(acc[i][jn][2], acc[i][jn][3]);
            }
        }
    } else {
        // emode 1: stage to smem (XOR-swizzled float2), rope pairs (d, d+64), fp16 head-major
        float2* F2 = (float2*)smraw;
#pragma unroll
        for (int i = 0; i < 4; i++) {
            int rl0 = wm + i * 16 + mrow;
            int rl1 = rl0 + 8;
#pragma unroll
            for (int jn = 0; jn < 4; jn++) {
                int c2 = (wn + jn * 8 + ncol) >> 1;
                F2[rl0 * 64 + (c2 ^ (rl0 & 15))] = make_float2(acc[i][jn][0], acc[i][jn][1]);
                F2[rl1 * 64 + (c2 ^ (rl1 & 15))] = make_float2(acc[i][jn][2], acc[i][jn][3]);
            }
        }
        __syncthreads();

#pragma unroll
        for (int pass = 0; pass < 16; pass++) {
            int r = pass * 8 + (tid >> 5);
            float2 t1 = F2[r * 64 + (lane ^ (r & 15))];
            float2 t2 = F2[r * 64 + ((lane + 32) ^ (r & 15))];
            int d = lane * 2;
            int grow = row0 + r;
            int s = grow & (SEQ - 1), bb = grow >> 11;
            float ca = g_cos[s * 64 + d], cb = g_cos[s * 64 + d + 1];
            float sa = g_sin[s * 64 + d], sb = g_sin[s * 64 + d + 1];
            size_t base = (((size_t)bb * nh + head) * SEQ + s) * HD;
            *(uint32_t*)(Hd + base + d) = pk2(t1.x * ca - t2.x * sa, t1.y * cb - t2.y * sb);
            *(uint32_t*)(Hd + base + d + 64) = pk2(t2.x * ca + t1.x * sa, t2.y * cb + t1.y * sb);
        }
    }
}

// ---------------- attention via mma.sync (fp16), 2-stage, work-descending schedule ----------------
#define AT_SMEM (98304)

__global__ __launch_bounds__(256) void attn_mma(
    const __half* __restrict__ Qh, const __half* __restrict__ Kh,
    const __half* __restrict__ Vh, __half* __restrict__ Oh) {
    extern __shared__ char smraw[];
    const uint32_t S0 = smem_u32(smraw);
    const int tid = threadIdx.x;
    const int lane = tid & 31, wid = tid >> 5;
    const int qt = gridDim.x - 1 - blockIdx.x;  // heavy tiles first
    const int h = blockIdx.y, b = blockIdx.z;
    const int g = h >> 2;
    const int q0 = qt * 128;
    const int m0 = wid * 16;

    {
        const char* qb = (const char*)(Qh + (((size_t)b * HQ + h) * SEQ + q0) * HD);
#pragma unroll
        for (int p = 0; p < 8; p++) {
            int u = tid + (p << 8);
            int r = u >> 4, c = u & 15;
            cp16(S0 + r * 256 + (uint32_t)((c ^ (r & 7)) << 4), qb + r * 256 + c * 16);
        }
    }

    const size_t kvhead = ((size_t)b * HKV + g) * SEQ;
    const int kt_lo = max(0, q0 - WINDOW + 1) >> 6;
    const int kt_hi = (q0 + 127) >> 6;

    {
        const size_t kb = (kvhead + (size_t)kt_lo * 64) * HD;
        uint32_t B0 = S0 + 32768;
#pragma unroll
        for (int p = 0; p < 4; p++) {
            int u = tid + (p << 8);
            int r = u >> 4, c = u & 15;
            uint32_t off = r * 256 + (uint32_t)((c ^ (r & 7)) << 4);
            size_t go = (size_t)r * 256 + c * 16;
            cp16(B0 + off, (const char*)(Kh + kb) + go);
            cp16(B0 + 16384 + off, (const char*)(Vh + kb) + go);
        }
    }
    cp_commit();

    float acc[16][4];
#pragma unroll
    for (int i = 0; i < 16; i++)
#pragma unroll
        for (int j = 0; j < 4; j++) acc[i][j] = 0.f;
    float m_run0 = NEG_INF_F, m_run1 = NEG_INF_F, l_run0 = 0.f, l_run1 = 0.f;

    const int r0g = q0 + m0 + (lane >> 2);
    const int r1g = r0g + 8;
    const float qscale = 0.08838834764831845f;  // 1/sqrt(128)

    const int a_r = lane & 15;
    const int a_ch = lane >> 4;
    const int sb_r = (lane & 7) + ((lane & 16) >> 1);
    const int sb_c = (lane >> 3) & 1;
    const int pv_r = (lane & 7) + (lane & 8);
    const int pv_c = (lane & 16) >> 4;

    for (int kt = kt_lo; kt <= kt_hi; kt++) {
        const int buf = (kt - kt_lo) & 1;
        if (kt < kt_hi) {
            const size_t kb = (kvhead + (size_t)(kt + 1) * 64) * HD;
            uint32_t NB = S0 + 32768 + (buf ^ 1) * 32768;
#pragma unroll
            for (int p = 0; p < 4; p++) {
                int u = tid + (p << 8);
                int r = u >> 4, c = u & 15;
                uint32_t off = r * 256 + (uint32_t)((c ^ (r & 7)) << 4);
                size_t go = (size_t)r * 256 + c * 16;
                cp16(NB + off, (const char*)(Kh + kb) + go);
                cp16(NB + 16384 + off, (const char*)(Vh + kb) + go);
            }
            cp_commit();
            cp_wait1();
        } else {
            cp_wait0();
        }
        __syncthreads();

        const uint32_t KB = S0 + 32768 + buf * 32768;

        float S[8][4];
#pragma unroll
        for (int i = 0; i < 8; i++)
#pragma unroll
            for (int j = 0; j < 4; j++) S[i][j] = 0.f;

#pragma unroll
        for (int kc = 0; kc < 8; kc++) {
            uint32_t aH[4];
            {
                int r = m0 + a_r;
                uint32_t cl = (uint32_t)((2 * kc + a_ch) ^ (r & 7)) << 4;
                LDSM4(aH[0], aH[1], aH[2], aH[3], S0 + r * 256 + cl);
            }
#pragma unroll
            for (int np = 0; np < 4; np++) {
                int rr = np * 16 + sb_r;
                uint32_t cl = (uint32_t)((2 * kc + sb_c) ^ (rr & 7)) << 4;
                uint32_t bh0, bh1, bh2, bh3;
                LDSM4(bh0, bh1, bh2, bh3, KB + rr * 256 + cl);
                mma16816(S[2 * np], aH, bh0, bh1);
                mma16816(S[2 * np + 1], aH, bh2, bh3);
            }
        }

        // ---- poly tanh cap + mask + online softmax ----
        const int k0g = kt * 64;
        float mx0 = NEG_INF_F, mx1 = NEG_INF_F;
#pragma unroll
        for (int a = 0; a < 8; a++) {
            int cb = k0g + 8 * a + ((lane & 3) << 1);
            float v0 = captanh(S[a][0] * qscale);
            float v1 = captanh(S[a][1] * qscale);
            float v2 = captanh(S[a][2] * qscale);
            float v3 = captanh(S[a][3] * qscale);
            bool m00 = (cb <= r0g) && (cb > r0g - WINDOW);
            bool m01 = (cb + 1 <= r0g) && (cb + 1 > r0g - WINDOW);
            bool m10 = (cb <= r1g) && (cb > r1g - WINDOW);
            bool m11 = (cb + 1 <= r1g) && (cb + 1 > r1g - WINDOW);
            S[a][0] = m00 ? v0 : NEG_INF_F;
            S[a][1] = m01 ? v1 : NEG_INF_F;
            S[a][2] = m10 ? v2 : NEG_INF_F;
            S[a][3] = m11 ? v3 : NEG_INF_F;
            mx0 = fmaxf(mx0, fmaxf(S[a][0], S[a][1]));
            mx1 = fmaxf(mx1, fmaxf(S[a][2], S[a][3]));
        }
        mx0 = fmaxf(mx0, __shfl_xor_sync(~0u, mx0, 1));
        mx0 = fmaxf(mx0, __shfl_xor_sync(~0u, mx0, 2));
        mx1 = fmaxf(mx1, __shfl_xor_sync(~0u, mx1, 1));
        mx1 = fmaxf(mx1, __shfl_xor_sync(~0u, mx1, 2));

        float mn0 = fmaxf(m_run0, mx0), mn1 = fmaxf(m_run1, mx1);
        float cor0 = __expf(m_run0 - mn0), cor1 = __expf(m_run1 - mn1);
        float sum0 = 0.f, sum1 = 0.f;
#pragma unroll
        for (int a = 0; a < 8; a++) {
            float p0 = (S[a][0] > -1e29f) ? __expf(S[a][0] - mn0) : 0.f;
            float p1 = (S[a][1] > -1e29f) ? __expf(S[a][1] - mn0) : 0.f;
            float p2 = (S[a][2] > -1e29f) ? __expf(S[a][2] - mn1) : 0.f;
            float p3 = (S[a][3] > -1e29f) ? __expf(S[a][3] - mn1) : 0.f;
            S[a][0] = p0; S[a][1] = p1; S[a][2] = p2; S[a][3] = p3;
            sum0 += p0 + p1;
            sum1 += p2 + p3;
        }
        sum0 += __shfl_xor_sync(~0u, sum0, 1);
        sum0 += __shfl_xor_sync(~0u, sum0, 2);
        sum1 += __shfl_xor_sync(~0u, sum1, 1);
        sum1 += __shfl_xor_sync(~0u, sum1, 2);
        l_run0 = l_run0 * cor0 + sum0;
        l_run1 = l_run1 * cor1 + sum1;
        m_run0 = mn0;
        m_run1 = mn1;
#pragma unroll
        for (int i = 0; i < 16; i++) {
            acc[i][0] *= cor0; acc[i][1] *= cor0;
            acc[i][2] *= cor1; acc[i][3] *= cor1;
        }

        uint32_t pH[4][4];
#pragma unroll
        for (int j = 0; j < 4; j++) {
#pragma unroll
            for (int e = 0; e < 2; e++) {
                int a = 2 * j + e;
                pH[j][0 + 2 * e] = pk2(S[a][0], S[a][1]);
                pH[j][1 + 2 * e] = pk2(S[a][2], S[a][3]);
            }
        }

        const uint32_t VB = KB + 16384;
#pragma unroll
        for (int j = 0; j < 4; j++) {
            int kr = j * 16 + pv_r;
#pragma unroll
            for (int dp = 0; dp < 8; dp++) {
                uint32_t cch = (uint32_t)(2 * dp + pv_c);
                uint32_t addr = VB + kr * 256 + (((cch ^ (kr & 7))) << 4);
                uint32_t bh0, bh1, bh2, bh3;
                LDSM4T(bh0, bh1, bh2, bh3, addr);
                mma16816(acc[2 * dp], pH[j], bh0, bh1);
                mma16816(acc[2 * dp + 1], pH[j], bh2, bh3);
            }
        }
        __syncthreads();
    }

    const float inv0 = 1.f / l_run0, inv1 = 1.f / l_run1;
    const size_t gr0 = (size_t)b * SEQ + q0 + m0 + (lane >> 2);
    const size_t gr1 = gr0 + 8;
    const int colb = h * HD + ((lane & 3) << 1);
#pragma unroll
    for (int nd = 0; nd < 16; nd++) {
        int col = colb + nd * 8;
        *(uint32_t*)(Oh + gr0 * NQ + col) = pk2(acc[nd][0] * inv0, acc[nd][1] * inv0);
        *(uint32_t*)(Oh + gr1 * NQ + col) = pk2(acc[nd][2] * inv1, acc[nd][3] * inv1);
    }
}

// ---------------- launch ----------------
extern "C" void kernel_launch(void* const* d_in, const int* in_sizes, int n_in,
                              void* d_out, int out_size) {
    const float* x = (const float*)d_in[0];
    const float* gamma = (const float*)d_in[1];
    const float* Wq = (const float*)d_in[2];
    const float* Wk = (const float*)d_in[3];
    const float* Wv = (const float*)d_in[4];
    const float* Wo = (const float*)d_in[5];
    float* out = (float*)d_out;

    __half *xnh, *wqkv, *wo, *ath, *qh, *kh, *vh;
    float *cosT, *sinT;
    cudaGetSymbolAddress((void**)&xnh, g_xn_h);
    cudaGetSymbolAddress((void**)&wqkv, g_wqkvT);
    cudaGetSymbolAddress((void**)&wo, g_woT);
    cudaGetSymbolAddress((void**)&ath, g_at_h);
    cudaGetSymbolAddress((void**)&qh, g_qh);
    cudaGetSymbolAddress((void**)&kh, g_kh);
    cudaGetSymbolAddress((void**)&vh, g_vh);
    cudaGetSymbolAddress((void**)&cosT, g_cos);
    cudaGetSymbolAddress((void**)&sinT, g_sin);

    cudaFuncSetAttribute(gemm_mma, cudaFuncAttributeMaxDynamicSharedMemorySize, GEMM_SMEM);
    cudaFuncSetAttribute(attn_mma, cudaFuncAttributeMaxDynamicSharedMemorySize, AT_SMEM);

    // RoPE tables first (consumed by GEMM epilogues)
    rope_table_kernel<<<(SEQ * 64 + 255) / 256, 256>>>(cosT, sinT);

    // weight convert+transpose into packed QKV buffer + Wo
    {
        dim3 gq(HIDDEN / 64, NQ / 64);
        tconv_kernel<<<gq, 256>>>(Wq, wqkv, HIDDEN, NQ);
        dim3 gk(HIDDEN / 64, NKV / 64);
        tconv_kernel<<<gk, 256>>>(Wk, wqkv + (size_t)NQ * HIDDEN, HIDDEN, NKV);
        tconv_kernel<<<gk, 256>>>(Wv, wqkv + (size_t)(NQ + NKV) * HIDDEN, HIDDEN, NKV);
        dim3 go(NQ / 64, HIDDEN / 64);
        tconv_kernel<<<go, 256>>>(Wo, wo, NQ, HIDDEN);
    }

    // RMSNorm
    rmsnorm_kernel<<<MROWS, 256>>>(x, gamma, xnh);

    // fused QKV projection (mode 4)
    {
        dim3 gqkv(NQKV / 128, MROWS / 128);
        gemm_mma<<<gqkv, 256, GEMM_SMEM>>>(xnh, wqkv, (const float*)0, (float*)0,
                                           qh, kh, vh, 4, MROWS, NQKV, HIDDEN);
    }

    // attention
    {
        dim3 ga(SEQ / 128, HQ, BATCH);
        attn_mma<<<ga, 256, AT_SMEM>>>(qh, kh, vh, ath);
    }

    // output projection + residual
    {
        dim3 go(HIDDEN / 128, MROWS / 128);
        gemm_mma<<<go, 256, GEMM_SMEM>>>(ath, wo, x, out, (__half*)0, (__half*)0, (__half*)0,
                                         0, MROWS, HIDDEN, NQ);
    }
}